// round 15
// baseline (speedup 1.0000x reference)
#include <cuda_runtime.h>
#include <cstdint>

// E[b] = sum over strict-lower-tri pairs (i,j) (row-major flat order):
//          decompFE_flat[b,p] * rsqrt(|coords[b,i]-coords[b,j]|^2)
//
// BPB=4 batches/block in ~94 KB dynamic smem. TMA bulk-copies all 4 flat rows;
// r^2 in FMA form (i-side staged as (-2x,-2y,-2z,n), j-side (x,y,z,n)).
// One iteration covers 128 pairs: all loop/address scaffolding amortized 4x.

#define BATCH   2048
#define NATOMS  100
#define NC2     4950
#define TPB     512
#define NWARPS  (TPB / 32)
#define BPB     4
#define COPY_BYTES (BPB * NC2 * 4)           // 79200, multiple of 16

#define SFLAT_LEN (BPB * NC2 + 64)           // padded
#define SC_LEN    (128 * BPB * 4)            // [atom][q][4]
#define SMEM_DYN  ((SFLAT_LEN + 2 * SC_LEN) * 4)

__device__ __forceinline__ uint32_t smem_u32(const void* p) {
    uint32_t a;
    asm("{ .reg .u64 t; cvta.to.shared.u64 t, %1; cvt.u32.u64 %0, t; }"
        : "=r"(a) : "l"(p));
    return a;
}

__global__ __launch_bounds__(TPB, 2)
void eij_kernel(const float* __restrict__ coords,
                const float* __restrict__ flat,
                float* __restrict__ out)
{
    extern __shared__ float smem[];
    float* sflat = smem;                        // SFLAT_LEN
    float* scA   = smem + SFLAT_LEN;            // i-side (-2x,-2y,-2z,n)
    float* scB   = scA + SC_LEN;                // j-side ( x,  y,  z, n)

    __shared__ float wred[BPB][NWARPS];
    __shared__ __align__(8) unsigned long long mbar;

    const int b0   = blockIdx.x * BPB;
    const int t    = threadIdx.x;
    const int lane = t & 31;
    const int wid  = t >> 5;

    const uint32_t mb = smem_u32(&mbar);

    if (t == 0)
        asm volatile("mbarrier.init.shared.b64 [%0], 1;" :: "r"(mb) : "memory");
    __syncthreads();

    if (t == 0) {
        const uint32_t dst = smem_u32(sflat);
        const float* src = flat + (size_t)b0 * NC2;     // 16B-aligned
        asm volatile("mbarrier.arrive.expect_tx.shared.b64 _, [%0], %1;"
                     :: "r"(mb), "r"((unsigned)COPY_BYTES) : "memory");
        asm volatile("cp.async.bulk.shared::cta.global.mbarrier::complete_tx::bytes"
                     " [%0], [%1], %2, [%3];"
                     :: "r"(dst), "l"(src), "r"((unsigned)COPY_BYTES), "r"(mb)
                     : "memory");
    }

    // stage coords: one (atom, q) per thread; atoms >= NATOMS zero-padded
    for (int k = t; k < 128 * BPB; k += TPB) {
        const int atom = k >> 2;
        const int q    = k & 3;
        float x = 0.f, y = 0.f, z = 0.f;
        if (atom < NATOMS) {
            const float* cp = coords + (size_t)(b0 + q) * (NATOMS * 3) + atom * 3;
            x = cp[0]; y = cp[1]; z = cp[2];
        }
        const float n = fmaf(x, x, fmaf(y, y, z * z));
        *(float4*)&scB[(atom * BPB + q) * 4] = make_float4(x, y, z, n);
        *(float4*)&scA[(atom * BPB + q) * 4] =
            make_float4(-2.f * x, -2.f * y, -2.f * z, n);
    }
    __syncthreads();

    // wait for the flat tile
    {
        uint32_t done;
        do {
            asm volatile("{ .reg .pred p;"
                         "  mbarrier.try_wait.parity.shared.b64 p, [%1], 0, 0x989680;"
                         "  selp.b32 %0, 1, 0, p; }"
                         : "=r"(done) : "r"(mb) : "memory");
        } while (!done);
    }

    float acc0 = 0.f, acc1 = 0.f, acc2 = 0.f, acc3 = 0.f;

    #pragma unroll
    for (int jb = 0; jb < 4; ++jb) {
        const int jbase = jb * 32;
        const int j = jbase + lane;                 // padded arrays: safe

        const float4 cj0 = *(const float4*)&scB[(j * BPB + 0) * 4];
        const float4 cj1 = *(const float4*)&scB[(j * BPB + 1) * 4];
        const float4 cj2 = *(const float4*)&scB[(j * BPB + 2) * 4];
        const float4 cj3 = *(const float4*)&scB[(j * BPB + 3) * 4];

        // ---- diagonal rows (masked accumulate only) ----
        {
            int i    = jbase + 1 + wid;
            int off  = i * (i - 1) / 2 + jbase + lane;
            int step = NWARPS * i + (NWARPS * (NWARPS - 1)) / 2;
            const int iend = (jbase + 32 < NATOMS) ? jbase + 32 : NATOMS - 1;

            for (; i <= iend; i += NWARPS) {
                const bool valid = lane < (i - jbase);

                const float v0 = sflat[off];
                const float v1 = sflat[off + NC2];
                const float v2 = sflat[off + 2 * NC2];
                const float v3 = sflat[off + 3 * NC2];

                const float4 a0 = *(const float4*)&scA[(i * BPB + 0) * 4];
                const float4 a1 = *(const float4*)&scA[(i * BPB + 1) * 4];
                const float4 a2 = *(const float4*)&scA[(i * BPB + 2) * 4];
                const float4 a3 = *(const float4*)&scA[(i * BPB + 3) * 4];

                const float r0 = fmaf(a0.x, cj0.x, fmaf(a0.y, cj0.y,
                                 fmaf(a0.z, cj0.z, a0.w + cj0.w)));
                const float r1 = fmaf(a1.x, cj1.x, fmaf(a1.y, cj1.y,
                                 fmaf(a1.z, cj1.z, a1.w + cj1.w)));
                const float r2 = fmaf(a2.x, cj2.x, fmaf(a2.y, cj2.y,
                                 fmaf(a2.z, cj2.z, a2.w + cj2.w)));
                const float r3 = fmaf(a3.x, cj3.x, fmaf(a3.y, cj3.y,
                                 fmaf(a3.z, cj3.z, a3.w + cj3.w)));

                const float q0 = rsqrtf(r0), q1 = rsqrtf(r1);
                const float q2 = rsqrtf(r2), q3 = rsqrtf(r3);

                if (valid) acc0 = fmaf(v0, q0, acc0);
                if (valid) acc1 = fmaf(v1, q1, acc1);
                if (valid) acc2 = fmaf(v2, q2, acc2);
                if (valid) acc3 = fmaf(v3, q3, acc3);

                off  += step;
                step += NWARPS * NWARPS;
            }
        }

        // ---- full rows (no predication) ----
        {
            int i    = jbase + 33 + wid;
            int off  = i * (i - 1) / 2 + jbase + lane;
            int step = NWARPS * i + (NWARPS * (NWARPS - 1)) / 2;

            #pragma unroll 2
            for (; i < NATOMS; i += NWARPS) {
                const float v0 = sflat[off];
                const float v1 = sflat[off + NC2];
                const float v2 = sflat[off + 2 * NC2];
                const float v3 = sflat[off + 3 * NC2];

                const float4 a0 = *(const float4*)&scA[(i * BPB + 0) * 4];
                const float4 a1 = *(const float4*)&scA[(i * BPB + 1) * 4];
                const float4 a2 = *(const float4*)&scA[(i * BPB + 2) * 4];
                const float4 a3 = *(const float4*)&scA[(i * BPB + 3) * 4];

                const float r0 = fmaf(a0.x, cj0.x, fmaf(a0.y, cj0.y,
                                 fmaf(a0.z, cj0.z, a0.w + cj0.w)));
                const float r1 = fmaf(a1.x, cj1.x, fmaf(a1.y, cj1.y,
                                 fmaf(a1.z, cj1.z, a1.w + cj1.w)));
                const float r2 = fmaf(a2.x, cj2.x, fmaf(a2.y, cj2.y,
                                 fmaf(a2.z, cj2.z, a2.w + cj2.w)));
                const float r3 = fmaf(a3.x, cj3.x, fmaf(a3.y, cj3.y,
                                 fmaf(a3.z, cj3.z, a3.w + cj3.w)));

                acc0 = fmaf(v0, rsqrtf(r0), acc0);
                acc1 = fmaf(v1, rsqrtf(r1), acc1);
                acc2 = fmaf(v2, rsqrtf(r2), acc2);
                acc3 = fmaf(v3, rsqrtf(r3), acc3);

                off  += step;
                step += NWARPS * NWARPS;
            }
        }
    }

    // reductions
    #pragma unroll
    for (int off = 16; off > 0; off >>= 1) {
        acc0 += __shfl_down_sync(0xFFFFFFFFu, acc0, off);
        acc1 += __shfl_down_sync(0xFFFFFFFFu, acc1, off);
        acc2 += __shfl_down_sync(0xFFFFFFFFu, acc2, off);
        acc3 += __shfl_down_sync(0xFFFFFFFFu, acc3, off);
    }
    if (lane == 0) {
        wred[0][wid] = acc0; wred[1][wid] = acc1;
        wred[2][wid] = acc2; wred[3][wid] = acc3;
    }
    __syncthreads();

    if (wid == 0 && lane < NWARPS) {
        #pragma unroll
        for (int q = 0; q < BPB; ++q) {
            float s = wred[q][lane];
            #pragma unroll
            for (int off = NWARPS / 2; off > 0; off >>= 1)
                s += __shfl_down_sync(0xFFFFu, s, off);
            if (lane == 0) out[b0 + q] = s;
        }
    }
}

extern "C" void kernel_launch(void* const* d_in, const int* in_sizes, int n_in,
                              void* d_out, int out_size)
{
    const float* coords = (const float*)d_in[0];   // [2048, 100, 3]
    const float* flat   = (const float*)d_in[1];   // [2048, 4950]
    float* out          = (float*)d_out;           // [2048, 1]

    cudaFuncSetAttribute(eij_kernel,
                         cudaFuncAttributeMaxDynamicSharedMemorySize, SMEM_DYN);
    eij_kernel<<<BATCH / BPB, TPB, SMEM_DYN>>>(coords, flat, out);
}

// round 16
// speedup vs baseline: 1.3391x; 1.3391x over previous
#include <cuda_runtime.h>
#include <cstdint>

// E[b] = sum over strict-lower-tri pairs (i,j) (row-major flat order):
//          decompFE_flat[b,p] * rsqrt(|coords[b,i]-coords[b,j]|^2)
//
// Row-major loop, rows grouped by number of 32-wide j-steps so the inner
// step count is compile-time constant (no inner branches). cj coords in
// registers per group; ci per row via uniform LDS.128; v from TMA-staged smem.
// r^2 = ni + nj - 2*(ci.cj) via FMA chain. BPB=2, TPB=256, 5 blocks/SM.

#define BATCH   2048
#define NATOMS  100
#define NC2     4950
#define TPB     256
#define NWARPS  (TPB / 32)
#define BPB     2
#define COPY_BYTES (BPB * NC2 * 4)      // 39600, multiple of 16
#define SFLAT_LEN (BPB * NC2 + 32)      // padded for masked-step overreads

__device__ __forceinline__ uint32_t smem_u32(const void* p) {
    uint32_t a;
    asm("{ .reg .u64 t; cvta.to.shared.u64 t, %1; cvt.u32.u64 %0, t; }"
        : "=r"(a) : "l"(p));
    return a;
}

template<int NFULL>
__device__ __forceinline__ void rows_group(
    int lo, int hi, int wid, int lane,
    const float4* __restrict__ scB4, const float* __restrict__ sflat,
    float& acc0, float& acc1)
{
    // group-scoped lane-resident j coords (x, y, z, n) per batch
    float4 cj0[NFULL + 1], cj1[NFULL + 1];
    #pragma unroll
    for (int jb = 0; jb <= NFULL; ++jb) {
        const int j = jb * 32 + lane;          // scB4 padded to 128 atoms
        cj0[jb] = scB4[j * 2 + 0];
        cj1[jb] = scB4[j * 2 + 1];
    }

    for (int i = lo + wid; i <= hi; i += NWARPS) {
        const float4 ci0 = scB4[i * 2 + 0];    // warp-uniform LDS.128
        const float4 ci1 = scB4[i * 2 + 1];
        int off = i * (i - 1) / 2 + lane;

        #pragma unroll
        for (int jb = 0; jb < NFULL; ++jb, off += 32) {
            const float v0 = sflat[off];
            const float v1 = sflat[off + NC2];

            const float d0 = fmaf(ci0.x, cj0[jb].x,
                             fmaf(ci0.y, cj0[jb].y, ci0.z * cj0[jb].z));
            const float r0 = fmaf(-2.f, d0, ci0.w + cj0[jb].w);
            const float d1 = fmaf(ci1.x, cj1[jb].x,
                             fmaf(ci1.y, cj1[jb].y, ci1.z * cj1[jb].z));
            const float r1 = fmaf(-2.f, d1, ci1.w + cj1[jb].w);

            acc0 = fmaf(v0, rsqrtf(r0), acc0);
            acc1 = fmaf(v1, rsqrtf(r1), acc1);
        }

        // masked (diagonal) step: jb == NFULL
        {
            const bool valid = lane < (i - NFULL * 32);
            const float v0 = sflat[off];
            const float v1 = sflat[off + NC2];

            const float d0 = fmaf(ci0.x, cj0[NFULL].x,
                             fmaf(ci0.y, cj0[NFULL].y, ci0.z * cj0[NFULL].z));
            const float r0 = fmaf(-2.f, d0, ci0.w + cj0[NFULL].w);
            const float d1 = fmaf(ci1.x, cj1[NFULL].x,
                             fmaf(ci1.y, cj1[NFULL].y, ci1.z * cj1[NFULL].z));
            const float r1 = fmaf(-2.f, d1, ci1.w + cj1[NFULL].w);

            const float q0 = rsqrtf(r0);
            const float q1 = rsqrtf(r1);
            if (valid) acc0 = fmaf(v0, q0, acc0);
            if (valid) acc1 = fmaf(v1, q1, acc1);
        }
    }
}

__global__ __launch_bounds__(TPB, 5)
void eij_kernel(const float* __restrict__ coords,
                const float* __restrict__ flat,
                float* __restrict__ out)
{
    __shared__ float  sflat[SFLAT_LEN];          // 39728 B
    __shared__ float4 scB4[128 * BPB];           // (x,y,z,n), padded atoms
    __shared__ float  wred[BPB][NWARPS];
    __shared__ __align__(8) unsigned long long mbar;

    const int b0   = blockIdx.x * BPB;
    const int t    = threadIdx.x;
    const int lane = t & 31;
    const int wid  = t >> 5;

    const uint32_t mb = smem_u32(&mbar);

    if (t == 0)
        asm volatile("mbarrier.init.shared.b64 [%0], 1;" :: "r"(mb) : "memory");
    __syncthreads();

    if (t == 0) {
        const uint32_t dst = smem_u32(sflat);
        const float* src = flat + (size_t)b0 * NC2;   // 16B-aligned segment
        asm volatile("mbarrier.arrive.expect_tx.shared.b64 _, [%0], %1;"
                     :: "r"(mb), "r"((unsigned)COPY_BYTES) : "memory");
        asm volatile("cp.async.bulk.shared::cta.global.mbarrier::complete_tx::bytes"
                     " [%0], [%1], %2, [%3];"
                     :: "r"(dst), "l"(src), "r"((unsigned)COPY_BYTES), "r"(mb)
                     : "memory");
    }

    // stage coords: one (atom, q) per thread; atoms >= NATOMS zero-padded
    for (int k = t; k < 128 * BPB; k += TPB) {
        const int atom = k >> 1;
        const int q    = k & 1;
        float x = 0.f, y = 0.f, z = 0.f;
        if (atom < NATOMS) {
            const float* cp = coords + (size_t)(b0 + q) * (NATOMS * 3) + atom * 3;
            x = cp[0]; y = cp[1]; z = cp[2];
        }
        const float n = fmaf(x, x, fmaf(y, y, z * z));
        scB4[atom * 2 + q] = make_float4(x, y, z, n);
    }
    __syncthreads();

    // wait for the flat tile
    {
        uint32_t done;
        do {
            asm volatile("{ .reg .pred p;"
                         "  mbarrier.try_wait.parity.shared.b64 p, [%1], 0, 0x989680;"
                         "  selp.b32 %0, 1, 0, p; }"
                         : "=r"(done) : "r"(mb) : "memory");
        } while (!done);
    }

    float acc0 = 0.0f, acc1 = 0.0f;

    rows_group<0>( 1, 32, wid, lane, scB4, sflat, acc0, acc1);
    rows_group<1>(33, 64, wid, lane, scB4, sflat, acc0, acc1);
    rows_group<2>(65, 96, wid, lane, scB4, sflat, acc0, acc1);
    rows_group<3>(97, 99, wid, lane, scB4, sflat, acc0, acc1);

    // reductions
    #pragma unroll
    for (int off = 16; off > 0; off >>= 1) {
        acc0 += __shfl_down_sync(0xFFFFFFFFu, acc0, off);
        acc1 += __shfl_down_sync(0xFFFFFFFFu, acc1, off);
    }
    if (lane == 0) { wred[0][wid] = acc0; wred[1][wid] = acc1; }
    __syncthreads();

    if (wid == 0 && lane < NWARPS) {
        float s0 = wred[0][lane];
        float s1 = wred[1][lane];
        #pragma unroll
        for (int off = NWARPS / 2; off > 0; off >>= 1) {
            s0 += __shfl_down_sync(0xFFu, s0, off);
            s1 += __shfl_down_sync(0xFFu, s1, off);
        }
        if (lane == 0) { out[b0] = s0; out[b0 + 1] = s1; }
    }
}

extern "C" void kernel_launch(void* const* d_in, const int* in_sizes, int n_in,
                              void* d_out, int out_size)
{
    const float* coords = (const float*)d_in[0];   // [2048, 100, 3]
    const float* flat   = (const float*)d_in[1];   // [2048, 4950]
    float* out          = (float*)d_out;           // [2048, 1]

    eij_kernel<<<BATCH / BPB, TPB>>>(coords, flat, out);
}